// round 15
// baseline (speedup 1.0000x reference)
#include <cuda_runtime.h>
#include <cuda_bf16.h>
#include <cstdint>

// Problem constants
#define NN 8192
#define DD 1024
#define BM 128
#define BN 128
#define BK 64
#define NCH (DD / BK)          // 16 K-chunks
#define NTILE (NN / BM)        // 64
#define GSLOTS 304             // concurrent CTAs: 2/SM x 152 SMs (GB300)
#define MAX_GRID (2080 + 2 * GSLOTS)

// SMEM: stage s at s*32768 (A 16KB + B up-to-16KB per stage), 2 stages
#define STAGE_BYTES 32768
#define SMEM_BYTES (2 * STAGE_BYTES)

// Scratch (device globals: allocation-free)
__device__ __nv_bfloat16 g_perm_bf16[NN * DD];   // rows in permuted order: refs first
__device__ float g_all[NN];                      // indexed by PERMUTED position
__device__ float g_pos[NN];
__device__ int g_perm[NN];                       // perm[k] = original row index
__device__ int g_nref;

// ---------------- helpers ----------------
__device__ __forceinline__ uint32_t smem_to_u32(const void* p) {
    uint32_t a;
    asm("{ .reg .u64 t; cvta.to.shared.u64 t, %1; cvt.u32.u64 %0, t; }" : "=r"(a) : "l"(p));
    return a;
}
#define SW128(o) ((o) ^ (((o) >> 3) & 0x70))

__device__ __forceinline__ void cp_async16(uint32_t s, const void* g) {
    asm volatile("cp.async.cg.shared.global [%0], [%1], 16;" :: "r"(s), "l"(g));
}
#define CP_COMMIT() asm volatile("cp.async.commit_group;" ::: "memory")
#define CP_WAIT(n) asm volatile("cp.async.wait_group %0;" :: "n"(n) : "memory")

__device__ __forceinline__ void ldsm_x4(uint32_t* r, uint32_t addr) {
    asm volatile("ldmatrix.sync.aligned.m8n8.x4.shared.b16 {%0,%1,%2,%3}, [%4];"
                 : "=r"(r[0]), "=r"(r[1]), "=r"(r[2]), "=r"(r[3]) : "r"(addr));
}

__device__ __forceinline__ void mma16816(float* c, const uint32_t* a, const uint32_t* b) {
    asm("mma.sync.aligned.m16n8k16.row.col.f32.bf16.bf16.f32 "
        "{%0,%1,%2,%3}, {%4,%5,%6,%7}, {%8,%9}, {%0,%1,%2,%3};"
        : "+f"(c[0]), "+f"(c[1]), "+f"(c[2]), "+f"(c[3])
        : "r"(a[0]), "r"(a[1]), "r"(a[2]), "r"(a[3]), "r"(b[0]), "r"(b[1]));
}

// Map linear valid-tile index t -> (bi, bj). Valid set: fully-ref row tiles
// (bi < FT): bj in [bi, NTILE-1]; partial row tile (bi == FT < RT): bj in [0, NTILE-1].
__device__ __forceinline__ bool map_tile(int t, int nref, int* bi, int* bj) {
    int FT = nref >> 7;
    int RT = (nref + 127) >> 7;
    for (int r = 0; r < RT; r++) {
        int cnt = (r < FT) ? (NTILE - r) : NTILE;
        if (t < cnt) { *bi = r; *bj = (r < FT) ? (r + t) : t; return true; }
        t -= cnt;
    }
    return false;
}

// ---------------- Kernel 1: permutation (refs first) + zero accumulators + zero out ----------------
__global__ void compact_kernel(const int* __restrict__ labels, float* __restrict__ out) {
    __shared__ int wsum[32];
    __shared__ int s_nref;
    int t = threadIdx.x;            // 1024 threads, 8 elements each
    int lane = t & 31, warp = t >> 5;

#pragma unroll
    for (int i = 0; i < 8; i++) {
        g_all[t + i * 1024] = 0.0f;
        g_pos[t + i * 1024] = 0.0f;
    }
    if (t == 0) out[0] = 0.0f;

    int base = t * 8;
    int lab[8];
    int cnt = 0;
#pragma unroll
    for (int k = 0; k < 8; k++) {
        lab[k] = (labels[base + k] > 0) ? 1 : 0;
        cnt += lab[k];
    }
    int v = cnt;
#pragma unroll
    for (int o = 1; o < 32; o <<= 1) {
        int n = __shfl_up_sync(0xffffffffu, v, o);
        if (lane >= o) v += n;
    }
    int excl = v - cnt;
    if (lane == 31) wsum[warp] = v;
    __syncthreads();
    if (warp == 0) {
        int w = wsum[lane];
#pragma unroll
        for (int o = 1; o < 32; o <<= 1) {
            int n = __shfl_up_sync(0xffffffffu, w, o);
            if (lane >= o) w += n;
        }
        wsum[lane] = w;
        if (lane == 31) s_nref = w;
    }
    __syncthreads();
    int nref = s_nref;
    int ones_before = excl + (warp > 0 ? wsum[warp - 1] : 0);
#pragma unroll
    for (int k = 0; k < 8; k++) {
        int p = base + k;
        if (lab[k]) {
            g_perm[ones_before] = p;
            ones_before++;
        } else {
            g_perm[nref + p - ones_before] = p;
        }
    }
    if (t == 0) g_nref = nref;
}

// ---------------- Kernel 2: fused fp32->bf16 convert + permute gather ----------------
__global__ void convgather_kernel(const float* __restrict__ emb) {
    int r = blockIdx.x;
    int t = threadIdx.x;   // 128 threads
    int src = g_perm[r];
    const float4* s = reinterpret_cast<const float4*>(emb + (size_t)src * DD);
    __nv_bfloat162* d = reinterpret_cast<__nv_bfloat162*>(g_perm_bf16 + (size_t)r * DD);
#pragma unroll
    for (int i = 0; i < 2; i++) {
        int idx = t + i * 128;   // 0..255 float4 units
        float4 v = s[idx];
        d[idx * 2 + 0] = __floats2bfloat162_rn(v.x, v.y);
        d[idx * 2 + 1] = __floats2bfloat162_rn(v.z, v.w);
    }
}

// ---------------- Kernel 3: fused GEMM + exp + row/col reduce ----------------
// Load [ROWS x 64K] bf16 tile (SW128, 128B rows) via cp.async. UNITS = ROWS*8.
template <int ITERS>
__device__ __forceinline__ void load_tileT(uint32_t sbase, const __nv_bfloat16* gbase, int kc) {
    int tid = threadIdx.x;
#pragma unroll
    for (int i = 0; i < ITERS; i++) {
        int idx = tid + i * 256;
        int row = idx >> 3;
        int u = idx & 7;
        const void* g = gbase + (size_t)row * DD + kc * BK + u * 8;
        uint32_t off = (uint32_t)(row * 128 + u * 16);
        cp_async16(sbase + SW128(off), g);
    }
}

// Tile worker. NTT = number of 8-col n-subtiles per warp (8 -> 128-wide tile, 4 -> 64-wide).
template <int NTT>
__device__ __forceinline__ void tile_body(int bi, int bj, int col0, int nref, int FT,
                                          uint32_t sb) {
    constexpr int BCOLS = NTT * 16;                    // tile width in columns
    bool dual = (bj < FT) && (bi < bj);                // mirror tile skipped -> col sums
    int mode = (col0 + BCOLS <= nref) ? 2 : ((col0 >= nref) ? 0 : 1);

    int tid = threadIdx.x;
    int wid = tid >> 5, lid = tid & 31;
    int wm = wid & 3;      // warp row   (4)
    int wn = wid >> 2;     // warp col   (2)
    int grp = lid >> 2;    // groupID 0..7
    int tig = lid & 3;     // thread in group

    const __nv_bfloat16* Ab = g_perm_bf16 + (size_t)bi * BM * DD;
    const __nv_bfloat16* Bb = g_perm_bf16 + (size_t)col0 * DD;

    // ---- ldmatrix per-thread base offsets ----
    int g8 = lid >> 3, lr = lid & 7;
    uint32_t offA[2], offB[NTT / 2];
#pragma unroll
    for (int mt = 0; mt < 2; mt++) {
        int row = wm * 32 + mt * 16 + (g8 & 1) * 8 + lr;
        uint32_t c = ((g8 >> 1) * 16) ^ ((row & 7) * 16);
        offA[mt] = (uint32_t)(row * 128) + c;
    }
#pragma unroll
    for (int ntp = 0; ntp < NTT / 2; ntp++) {
        int row = wn * (NTT * 8) + ntp * 16 + (g8 >> 1) * 8 + lr;
        uint32_t c = ((g8 & 1) * 16) ^ ((row & 7) * 16);
        offB[ntp] = (uint32_t)(row * 128) + c;
    }

    float acc[2][NTT][4];
#pragma unroll
    for (int mt = 0; mt < 2; mt++)
#pragma unroll
        for (int nt = 0; nt < NTT; nt++)
#pragma unroll
            for (int e = 0; e < 4; e++) acc[mt][nt][e] = 0.0f;

    // Prologue: chunk 0 -> stage 0
    load_tileT<4>(sb, Ab, 0);
    load_tileT<NTT / 2>(sb + 16384, Bb, 0);
    CP_COMMIT();

    for (int c = 0; c < NCH; c++) {
        int s = c & 1;
        if (c + 1 < NCH) {
            int t2 = s ^ 1;
            load_tileT<4>(sb + t2 * STAGE_BYTES, Ab, c + 1);
            load_tileT<NTT / 2>(sb + t2 * STAGE_BYTES + 16384, Bb, c + 1);
            CP_COMMIT();
            CP_WAIT(1);
        } else {
            CP_WAIT(0);
        }
        __syncthreads();

        uint32_t As = sb + s * STAGE_BYTES;
        uint32_t Bs = As + 16384;
#pragma unroll
        for (int kk = 0; kk < 4; kk++) {
            uint32_t xk = (uint32_t)(kk << 5);
            uint32_t a[2][4], b[NTT][2];
            ldsm_x4(a[0], (As + offA[0]) ^ xk);
            ldsm_x4(a[1], (As + offA[1]) ^ xk);
#pragma unroll
            for (int ntp = 0; ntp < NTT / 2; ntp++) {
                uint32_t r[4];
                ldsm_x4(r, (Bs + offB[ntp]) ^ xk);
                b[2 * ntp][0] = r[0]; b[2 * ntp][1] = r[1];
                b[2 * ntp + 1][0] = r[2]; b[2 * ntp + 1][1] = r[3];
            }
#pragma unroll
            for (int mt = 0; mt < 2; mt++)
#pragma unroll
                for (int nt = 0; nt < NTT; nt++)
                    mma16816(acc[mt][nt], a[mt], b[nt]);
        }
        __syncthreads();
    }

    // ---- Fused epilogue ----
    float cs[NTT][2];
    if (dual) {
#pragma unroll
        for (int nt = 0; nt < NTT; nt++) { cs[nt][0] = 0.0f; cs[nt][1] = 0.0f; }
    }

#pragma unroll
    for (int mt = 0; mt < 2; mt++) {
        int ri_lo = bi * BM + wm * 32 + mt * 16 + grp;   // permuted row index
        int ri_hi = ri_lo + 8;
        float sa0 = 0.f, sp0 = 0.f, sa1 = 0.f, sp1 = 0.f;
#pragma unroll
        for (int nt = 0; nt < NTT; nt++) {
            int c0 = wn * (NTT * 8) + nt * 8 + tig * 2;
#pragma unroll
            for (int e = 0; e < 2; e++) {
                int jg = col0 + c0 + e;                  // permuted col index
                float elo = __expf(10.0f * acc[mt][nt][e]);
                if (jg == ri_lo) elo = 0.0f;             // self-similarity
                float ehi = __expf(10.0f * acc[mt][nt][2 + e]);
                if (jg == ri_hi) ehi = 0.0f;
                sa0 += elo;
                sa1 += ehi;
                if (mode == 1) {
                    float l = (jg < nref) ? 1.0f : 0.0f;
                    sp0 += elo * l;
                    sp1 += ehi * l;
                }
                if (dual) cs[nt][e] += elo + ehi;        // column partial (rows are refs)
            }
        }
#pragma unroll
        for (int o = 1; o < 4; o <<= 1) {
            sa0 += __shfl_xor_sync(0xffffffff, sa0, o);
            sa1 += __shfl_xor_sync(0xffffffff, sa1, o);
        }
        if (mode == 1) {
#pragma unroll
            for (int o = 1; o < 4; o <<= 1) {
                sp0 += __shfl_xor_sync(0xffffffff, sp0, o);
                sp1 += __shfl_xor_sync(0xffffffff, sp1, o);
            }
        }
        if (tig == 0) {
            float p0 = (mode == 2) ? sa0 : sp0;
            float p1 = (mode == 2) ? sa1 : sp1;
            if (ri_lo < nref) {
                atomicAdd(&g_all[ri_lo], sa0);
                if (mode != 0) atomicAdd(&g_pos[ri_lo], p0);
            }
            if (ri_hi < nref) {
                atomicAdd(&g_all[ri_hi], sa1);
                if (mode != 0) atomicAdd(&g_pos[ri_hi], p1);
            }
        }
    }

    if (dual) {
        // Column sums -> row sums of the skipped mirror tile (pos == all there).
#pragma unroll
        for (int nt = 0; nt < NTT; nt++) {
#pragma unroll
            for (int e = 0; e < 2; e++) {
                float v = cs[nt][e];
                v += __shfl_xor_sync(0xffffffff, v, 4);
                v += __shfl_xor_sync(0xffffffff, v, 8);
                v += __shfl_xor_sync(0xffffffff, v, 16);
                if (lid < 4) {
                    int col = col0 + wn * (NTT * 8) + nt * 8 + lid * 2 + e;
                    atomicAdd(&g_all[col], v);
                    atomicAdd(&g_pos[col], v);
                }
            }
        }
    }
}

__global__ void __launch_bounds__(256, 2) gemm_exp_kernel() {
    int nref = g_nref;
    int FT = nref >> 7;
    int RT = (nref + 127) >> 7;
    // total valid tiles (closed form, matches map_tile)
    int T = FT * NTILE - (FT * (FT - 1)) / 2 + ((RT > FT) ? NTILE : 0);
    int R = T % GSLOTS;
    int F = T - R;

    extern __shared__ char smem[];
    uint32_t sb = smem_to_u32(smem);

    int id = blockIdx.x;
    if (id < F) {
        int bi, bj;
        map_tile(id, nref, &bi, &bj);
        tile_body<8>(bi, bj, bj * BN, nref, FT, sb);
    } else if (id < F + 2 * R) {
        int q = id - F;
        int bi, bj;
        map_tile(F + (q >> 1), nref, &bi, &bj);
        tile_body<4>(bi, bj, bj * BN + (q & 1) * 64, nref, FT, sb);
    }
}

// ---------------- Kernel 4: parallel loss reduce, direct to out ----------------
__global__ void finalize_partial(float* __restrict__ out) {
    int i = blockIdx.x * blockDim.x + threadIdx.x;
    int lane = threadIdx.x & 31, warp = threadIdx.x >> 5;
    __shared__ float s_part[8];
    int nref = g_nref;
    float loss = 0.0f;
    if (nref >= 2 && i < nref) {
        loss = -__logf(g_pos[i] / (g_all[i] + 1e-8f));
    }
#pragma unroll
    for (int o = 16; o > 0; o >>= 1) loss += __shfl_xor_sync(0xffffffffu, loss, o);
    if (lane == 0) s_part[warp] = loss;
    __syncthreads();
    if (warp == 0) {
        float v = (lane < 8) ? s_part[lane] : 0.0f;
#pragma unroll
        for (int o = 4; o > 0; o >>= 1) v += __shfl_xor_sync(0xffffffffu, v, o);
        if (lane == 0 && v != 0.0f) {
            atomicAdd(out, v / fmaxf((float)nref, 1.0f));
        }
    }
}

// ---------------- Launch ----------------
extern "C" void kernel_launch(void* const* d_in, const int* in_sizes, int n_in,
                              void* d_out, int out_size) {
    const float* emb = (const float*)d_in[0];
    const int* labels = (const int*)d_in[1];
    float* out = (float*)d_out;

    compact_kernel<<<1, 1024>>>(labels, out);
    convgather_kernel<<<NN, 128>>>(emb);

    cudaFuncSetAttribute(gemm_exp_kernel, cudaFuncAttributeMaxDynamicSharedMemorySize, SMEM_BYTES);
    gemm_exp_kernel<<<MAX_GRID, 256, SMEM_BYTES>>>();

    finalize_partial<<<NN / 256, 256>>>(out);
}

// round 16
// speedup vs baseline: 1.0062x; 1.0062x over previous
#include <cuda_runtime.h>
#include <cuda_bf16.h>
#include <cstdint>

// Problem constants
#define NN 8192
#define DD 1024
#define BM 128
#define BN 128
#define BK 64
#define NCH (DD / BK)          // 16 K-chunks
#define NTILE (NN / BM)        // 64
#define MAX_TILES 2080         // worst case: full upper triangle (nref = NN)

// SMEM: stage s at s*32768 (A 16KB + B 16KB per stage), 2 stages
#define STAGE_BYTES 32768
#define SMEM_BYTES (2 * STAGE_BYTES)

// Scratch (device globals: allocation-free)
__device__ __nv_bfloat16 g_perm_bf16[NN * DD];   // rows in permuted order: refs first
__device__ float g_all[NN];                      // indexed by PERMUTED position
__device__ float g_pos[NN];
__device__ int g_perm[NN];                       // perm[k] = original row index
__device__ int g_nref;

// ---------------- helpers ----------------
__device__ __forceinline__ uint32_t smem_to_u32(const void* p) {
    uint32_t a;
    asm("{ .reg .u64 t; cvta.to.shared.u64 t, %1; cvt.u32.u64 %0, t; }" : "=r"(a) : "l"(p));
    return a;
}
#define SW128(o) ((o) ^ (((o) >> 3) & 0x70))

__device__ __forceinline__ void cp_async16(uint32_t s, const void* g) {
    asm volatile("cp.async.cg.shared.global [%0], [%1], 16;" :: "r"(s), "l"(g));
}
#define CP_COMMIT() asm volatile("cp.async.commit_group;" ::: "memory")
#define CP_WAIT(n) asm volatile("cp.async.wait_group %0;" :: "n"(n) : "memory")

__device__ __forceinline__ void ldsm_x4(uint32_t* r, uint32_t addr) {
    asm volatile("ldmatrix.sync.aligned.m8n8.x4.shared.b16 {%0,%1,%2,%3}, [%4];"
                 : "=r"(r[0]), "=r"(r[1]), "=r"(r[2]), "=r"(r[3]) : "r"(addr));
}

__device__ __forceinline__ void mma16816(float* c, const uint32_t* a, const uint32_t* b) {
    asm volatile(
        "mma.sync.aligned.m16n8k16.row.col.f32.bf16.bf16.f32 "
        "{%0,%1,%2,%3}, {%4,%5,%6,%7}, {%8,%9}, {%0,%1,%2,%3};"
        : "+f"(c[0]), "+f"(c[1]), "+f"(c[2]), "+f"(c[3])
        : "r"(a[0]), "r"(a[1]), "r"(a[2]), "r"(a[3]), "r"(b[0]), "r"(b[1]));
}

// Map linear valid-tile index t -> (bi, bj). Valid set: fully-ref row tiles
// (bi < FT): bj in [bi, NTILE-1]; partial row tile (bi == FT < RT): bj in [0, NTILE-1].
__device__ __forceinline__ bool map_tile(int t, int nref, int* bi, int* bj) {
    int FT = nref >> 7;
    int RT = (nref + 127) >> 7;
    for (int r = 0; r < RT; r++) {
        int cnt = (r < FT) ? (NTILE - r) : NTILE;
        if (t < cnt) { *bi = r; *bj = (r < FT) ? (r + t) : t; return true; }
        t -= cnt;
    }
    return false;
}

// ---------------- Kernel 1: permutation (refs first) + zero out ----------------
__global__ void compact_kernel(const int* __restrict__ labels, float* __restrict__ out) {
    __shared__ int wsum[32];
    __shared__ int s_nref;
    int t = threadIdx.x;            // 1024 threads, 8 elements each
    int lane = t & 31, warp = t >> 5;

    if (t == 0) out[0] = 0.0f;

    int base = t * 8;
    int lab[8];
    int cnt = 0;
#pragma unroll
    for (int k = 0; k < 8; k++) {
        lab[k] = (labels[base + k] > 0) ? 1 : 0;
        cnt += lab[k];
    }
    int v = cnt;
#pragma unroll
    for (int o = 1; o < 32; o <<= 1) {
        int n = __shfl_up_sync(0xffffffffu, v, o);
        if (lane >= o) v += n;
    }
    int excl = v - cnt;
    if (lane == 31) wsum[warp] = v;
    __syncthreads();
    if (warp == 0) {
        int w = wsum[lane];
#pragma unroll
        for (int o = 1; o < 32; o <<= 1) {
            int n = __shfl_up_sync(0xffffffffu, w, o);
            if (lane >= o) w += n;
        }
        wsum[lane] = w;
        if (lane == 31) s_nref = w;
    }
    __syncthreads();
    int nref = s_nref;
    int ones_before = excl + (warp > 0 ? wsum[warp - 1] : 0);
#pragma unroll
    for (int k = 0; k < 8; k++) {
        int p = base + k;
        if (lab[k]) {
            g_perm[ones_before] = p;
            ones_before++;
        } else {
            g_perm[nref + p - ones_before] = p;
        }
    }
    if (t == 0) g_nref = nref;
}

// ---------------- Kernel 2: fp32->bf16 convert + permute gather + zero accumulators ----------------
__global__ void convgather_kernel(const float* __restrict__ emb) {
    int r = blockIdx.x;
    int t = threadIdx.x;   // 128 threads
    if (t == 0) { g_all[r] = 0.0f; g_pos[r] = 0.0f; }   // runs before the GEMM launch
    int src = g_perm[r];
    const float4* s = reinterpret_cast<const float4*>(emb + (size_t)src * DD);
    __nv_bfloat162* d = reinterpret_cast<__nv_bfloat162*>(g_perm_bf16 + (size_t)r * DD);
#pragma unroll
    for (int i = 0; i < 2; i++) {
        int idx = t + i * 128;   // 0..255 float4 units
        float4 v = s[idx];
        d[idx * 2 + 0] = __floats2bfloat162_rn(v.x, v.y);
        d[idx * 2 + 1] = __floats2bfloat162_rn(v.z, v.w);
    }
}

// ---------------- Kernel 3: fused GEMM + exp + row/col reduce (symmetric, 1D grid) ----------------
__device__ __forceinline__ void load_tile(uint32_t sbase, const __nv_bfloat16* gbase, int kc) {
    int tid = threadIdx.x;
#pragma unroll
    for (int i = 0; i < 4; i++) {
        int idx = tid + i * 256;         // 0..1023 16B-units
        int row = idx >> 3;
        int u = idx & 7;
        const void* g = gbase + (size_t)row * DD + kc * BK + u * 8;
        uint32_t off = (uint32_t)(row * 128 + u * 16);
        cp_async16(sbase + SW128(off), g);
    }
}

__global__ void __launch_bounds__(256, 2) gemm_exp_kernel() {
    int nref = g_nref;
    int bi, bj;
    if (!map_tile(blockIdx.x, nref, &bi, &bj)) return;
    int FT = nref >> 7;                                // count of fully-ref tiles
    bool dual = (bj < FT) && (bi < bj);                // upper off-diag ref x ref tile
    int mode = (BN * (bj + 1) <= nref) ? 2 : ((BN * bj >= nref) ? 0 : 1);

    extern __shared__ char smem[];
    uint32_t sb = smem_to_u32(smem);

    int tid = threadIdx.x;
    int wid = tid >> 5, lid = tid & 31;
    int wm = wid & 3;      // warp row   (4)
    int wn = wid >> 2;     // warp col   (2)
    int grp = lid >> 2;    // groupID 0..7
    int tig = lid & 3;     // thread in group

    const __nv_bfloat16* Ab = g_perm_bf16 + (size_t)bi * BM * DD;
    const __nv_bfloat16* Bb = g_perm_bf16 + (size_t)bj * BN * DD;

    // ---- ldmatrix per-thread base offsets (within a 16KB tile) ----
    int g8 = lid >> 3, lr = lid & 7;
    uint32_t offA[2], offB[4];
#pragma unroll
    for (int mt = 0; mt < 2; mt++) {
        int row = wm * 32 + mt * 16 + (g8 & 1) * 8 + lr;
        uint32_t c = ((g8 >> 1) * 16) ^ ((row & 7) * 16);
        offA[mt] = (uint32_t)(row * 128) + c;
    }
#pragma unroll
    for (int ntp = 0; ntp < 4; ntp++) {
        int row = wn * 64 + ntp * 16 + (g8 >> 1) * 8 + lr;
        uint32_t c = ((g8 & 1) * 16) ^ ((row & 7) * 16);
        offB[ntp] = (uint32_t)(row * 128) + c;
    }

    float acc[2][8][4];
#pragma unroll
    for (int mt = 0; mt < 2; mt++)
#pragma unroll
        for (int nt = 0; nt < 8; nt++)
#pragma unroll
            for (int e = 0; e < 4; e++) acc[mt][nt][e] = 0.0f;

    // Prologue: chunk 0 -> stage 0
    load_tile(sb, Ab, 0);
    load_tile(sb + 16384, Bb, 0);
    CP_COMMIT();

    for (int c = 0; c < NCH; c++) {
        int s = c & 1;
        if (c + 1 < NCH) {
            int t2 = s ^ 1;
            load_tile(sb + t2 * STAGE_BYTES, Ab, c + 1);
            load_tile(sb + t2 * STAGE_BYTES + 16384, Bb, c + 1);
            CP_COMMIT();
            CP_WAIT(1);
        } else {
            CP_WAIT(0);
        }
        __syncthreads();

        uint32_t As = sb + s * STAGE_BYTES;
        uint32_t Bs = As + 16384;
#pragma unroll
        for (int kk = 0; kk < 4; kk++) {
            uint32_t xk = (uint32_t)(kk << 5);
            uint32_t a[2][4], b[8][2];
            ldsm_x4(a[0], (As + offA[0]) ^ xk);
            ldsm_x4(a[1], (As + offA[1]) ^ xk);
#pragma unroll
            for (int ntp = 0; ntp < 4; ntp++) {
                uint32_t r[4];
                ldsm_x4(r, (Bs + offB[ntp]) ^ xk);
                b[2 * ntp][0] = r[0]; b[2 * ntp][1] = r[1];
                b[2 * ntp + 1][0] = r[2]; b[2 * ntp + 1][1] = r[3];
            }
#pragma unroll
            for (int mt = 0; mt < 2; mt++)
#pragma unroll
                for (int nt = 0; nt < 8; nt++)
                    mma16816(acc[mt][nt], a[mt], b[nt]);
        }
        __syncthreads();
    }

    // ---- Fused epilogue: exp, diag exclusion, row sums (+ col sums if dual) ----
    float cs[8][2];
    if (dual) {
#pragma unroll
        for (int nt = 0; nt < 8; nt++) { cs[nt][0] = 0.0f; cs[nt][1] = 0.0f; }
    }

#pragma unroll
    for (int mt = 0; mt < 2; mt++) {
        int ri_lo = bi * BM + wm * 32 + mt * 16 + grp;   // permuted row index
        int ri_hi = ri_lo + 8;
        float sa0 = 0.f, sp0 = 0.f, sa1 = 0.f, sp1 = 0.f;
#pragma unroll
        for (int nt = 0; nt < 8; nt++) {
            int c0 = wn * 64 + nt * 8 + tig * 2;
#pragma unroll
            for (int e = 0; e < 2; e++) {
                int jg = bj * BN + c0 + e;               // permuted col index
                float elo = __expf(10.0f * acc[mt][nt][e]);
                if (jg == ri_lo) elo = 0.0f;             // self-similarity
                float ehi = __expf(10.0f * acc[mt][nt][2 + e]);
                if (jg == ri_hi) ehi = 0.0f;
                sa0 += elo;
                sa1 += ehi;
                if (mode == 1) {
                    float l = (jg < nref) ? 1.0f : 0.0f;
                    sp0 += elo * l;
                    sp1 += ehi * l;
                }
                if (dual) cs[nt][e] += elo + ehi;        // column partial (rows are refs)
            }
        }
#pragma unroll
        for (int o = 1; o < 4; o <<= 1) {
            sa0 += __shfl_xor_sync(0xffffffff, sa0, o);
            sa1 += __shfl_xor_sync(0xffffffff, sa1, o);
        }
        if (mode == 1) {
#pragma unroll
            for (int o = 1; o < 4; o <<= 1) {
                sp0 += __shfl_xor_sync(0xffffffff, sp0, o);
                sp1 += __shfl_xor_sync(0xffffffff, sp1, o);
            }
        }
        if (tig == 0) {
            float p0 = (mode == 2) ? sa0 : sp0;
            float p1 = (mode == 2) ? sa1 : sp1;
            if (ri_lo < nref) {
                atomicAdd(&g_all[ri_lo], sa0);
                if (mode != 0) atomicAdd(&g_pos[ri_lo], p0);
            }
            if (ri_hi < nref) {
                atomicAdd(&g_all[ri_hi], sa1);
                if (mode != 0) atomicAdd(&g_pos[ri_hi], p1);
            }
        }
    }

    if (dual) {
        // Column sums -> row sums of the skipped mirror tile (pos == all there).
#pragma unroll
        for (int nt = 0; nt < 8; nt++) {
#pragma unroll
            for (int e = 0; e < 2; e++) {
                float v = cs[nt][e];
                v += __shfl_xor_sync(0xffffffff, v, 4);
                v += __shfl_xor_sync(0xffffffff, v, 8);
                v += __shfl_xor_sync(0xffffffff, v, 16);
                if (lid < 4) {
                    int col = bj * BN + wn * 64 + nt * 8 + lid * 2 + e;
                    atomicAdd(&g_all[col], v);
                    atomicAdd(&g_pos[col], v);
                }
            }
        }
    }
}

// ---------------- Kernel 4: parallel loss reduce, direct to out ----------------
__global__ void finalize_partial(float* __restrict__ out) {
    int i = blockIdx.x * blockDim.x + threadIdx.x;
    int lane = threadIdx.x & 31, warp = threadIdx.x >> 5;
    __shared__ float s_part[8];
    int nref = g_nref;
    float loss = 0.0f;
    if (nref >= 2 && i < nref) {
        loss = -__logf(g_pos[i] / (g_all[i] + 1e-8f));
    }
#pragma unroll
    for (int o = 16; o > 0; o >>= 1) loss += __shfl_xor_sync(0xffffffffu, loss, o);
    if (lane == 0) s_part[warp] = loss;
    __syncthreads();
    if (warp == 0) {
        float v = (lane < 8) ? s_part[lane] : 0.0f;
#pragma unroll
        for (int o = 4; o > 0; o >>= 1) v += __shfl_xor_sync(0xffffffffu, v, o);
        if (lane == 0 && v != 0.0f) {
            atomicAdd(out, v / fmaxf((float)nref, 1.0f));
        }
    }
}

// ---------------- Launch ----------------
extern "C" void kernel_launch(void* const* d_in, const int* in_sizes, int n_in,
                              void* d_out, int out_size) {
    const float* emb = (const float*)d_in[0];
    const int* labels = (const int*)d_in[1];
    float* out = (float*)d_out;

    compact_kernel<<<1, 1024>>>(labels, out);
    convgather_kernel<<<NN, 128>>>(emb);

    cudaFuncSetAttribute(gemm_exp_kernel, cudaFuncAttributeMaxDynamicSharedMemorySize, SMEM_BYTES);
    gemm_exp_kernel<<<MAX_TILES, 256, SMEM_BYTES>>>();

    finalize_partial<<<NN / 256, 256>>>(out);
}

// round 17
// speedup vs baseline: 1.0119x; 1.0056x over previous
#include <cuda_runtime.h>
#include <cuda_bf16.h>
#include <cstdint>

// Problem constants
#define NN 8192
#define DD 1024
#define BM 128
#define BN 128
#define BK 64
#define NCH (DD / BK)          // 16 K-chunks
#define NTILE (NN / BM)        // 64
#define MAX_TILES 2080         // worst case: full upper triangle (nref = NN)

// SMEM: stage s at s*32768 (A 16KB + B 16KB per stage), 2 stages
#define STAGE_BYTES 32768
#define SMEM_BYTES (2 * STAGE_BYTES)

// Scratch (device globals: allocation-free)
__device__ __nv_bfloat16 g_perm_bf16[NN * DD];   // rows in permuted order: refs first
__device__ float g_all[NN];                      // indexed by PERMUTED position
__device__ float g_pos[NN];
__device__ int g_perm[NN];                       // perm[k] = original row index
__device__ int g_nref;

// ---------------- helpers ----------------
__device__ __forceinline__ uint32_t smem_to_u32(const void* p) {
    uint32_t a;
    asm("{ .reg .u64 t; cvta.to.shared.u64 t, %1; cvt.u32.u64 %0, t; }" : "=r"(a) : "l"(p));
    return a;
}
#define SW128(o) ((o) ^ (((o) >> 3) & 0x70))

__device__ __forceinline__ void cp_async16(uint32_t s, const void* g) {
    asm volatile("cp.async.cg.shared.global [%0], [%1], 16;" :: "r"(s), "l"(g));
}
#define CP_COMMIT() asm volatile("cp.async.commit_group;" ::: "memory")
#define CP_WAIT(n) asm volatile("cp.async.wait_group %0;" :: "n"(n) : "memory")

__device__ __forceinline__ void ldsm_x4(uint32_t* r, uint32_t addr) {
    asm volatile("ldmatrix.sync.aligned.m8n8.x4.shared.b16 {%0,%1,%2,%3}, [%4];"
                 : "=r"(r[0]), "=r"(r[1]), "=r"(r[2]), "=r"(r[3]) : "r"(addr));
}

__device__ __forceinline__ void mma16816(float* c, const uint32_t* a, const uint32_t* b) {
    asm volatile(
        "mma.sync.aligned.m16n8k16.row.col.f32.bf16.bf16.f32 "
        "{%0,%1,%2,%3}, {%4,%5,%6,%7}, {%8,%9}, {%0,%1,%2,%3};"
        : "+f"(c[0]), "+f"(c[1]), "+f"(c[2]), "+f"(c[3])
        : "r"(a[0]), "r"(a[1]), "r"(a[2]), "r"(a[3]), "r"(b[0]), "r"(b[1]));
}

// Map linear valid-tile index t -> (bi, bj). Valid set: fully-ref row tiles
// (bi < FT): bj in [bi, NTILE-1]; partial row tile (bi == FT < RT): bj in [0, NTILE-1].
__device__ __forceinline__ bool map_tile(int t, int nref, int* bi, int* bj) {
    int FT = nref >> 7;
    int RT = (nref + 127) >> 7;
    for (int r = 0; r < RT; r++) {
        int cnt = (r < FT) ? (NTILE - r) : NTILE;
        if (t < cnt) { *bi = r; *bj = (r < FT) ? (r + t) : t; return true; }
        t -= cnt;
    }
    return false;
}

// ---------------- Kernel 1: permutation (refs first) + zero out ----------------
__global__ void compact_kernel(const int* __restrict__ labels, float* __restrict__ out) {
    __shared__ int wsum[32];
    __shared__ int s_nref;
    int t = threadIdx.x;            // 1024 threads, 8 elements each
    int lane = t & 31, warp = t >> 5;

    if (t == 0) out[0] = 0.0f;

    int base = t * 8;
    int lab[8];
    int cnt = 0;
#pragma unroll
    for (int k = 0; k < 8; k++) {
        lab[k] = (labels[base + k] > 0) ? 1 : 0;
        cnt += lab[k];
    }
    int v = cnt;
#pragma unroll
    for (int o = 1; o < 32; o <<= 1) {
        int n = __shfl_up_sync(0xffffffffu, v, o);
        if (lane >= o) v += n;
    }
    int excl = v - cnt;
    if (lane == 31) wsum[warp] = v;
    __syncthreads();
    if (warp == 0) {
        int w = wsum[lane];
#pragma unroll
        for (int o = 1; o < 32; o <<= 1) {
            int n = __shfl_up_sync(0xffffffffu, w, o);
            if (lane >= o) w += n;
        }
        wsum[lane] = w;
        if (lane == 31) s_nref = w;
    }
    __syncthreads();
    int nref = s_nref;
    int ones_before = excl + (warp > 0 ? wsum[warp - 1] : 0);
#pragma unroll
    for (int k = 0; k < 8; k++) {
        int p = base + k;
        if (lab[k]) {
            g_perm[ones_before] = p;
            ones_before++;
        } else {
            g_perm[nref + p - ones_before] = p;
        }
    }
    if (t == 0) g_nref = nref;
}

// ---------------- Kernel 2: fp32->bf16 convert + permute gather + zero accumulators ----------------
__global__ void convgather_kernel(const float* __restrict__ emb) {
    int r = blockIdx.x;
    int t = threadIdx.x;   // 128 threads
    if (t == 0) { g_all[r] = 0.0f; g_pos[r] = 0.0f; }   // runs before the GEMM launch
    int src = g_perm[r];
    const float4* s = reinterpret_cast<const float4*>(emb + (size_t)src * DD);
    __nv_bfloat162* d = reinterpret_cast<__nv_bfloat162*>(g_perm_bf16 + (size_t)r * DD);
#pragma unroll
    for (int i = 0; i < 2; i++) {
        int idx = t + i * 128;   // 0..255 float4 units
        float4 v = s[idx];
        d[idx * 2 + 0] = __floats2bfloat162_rn(v.x, v.y);
        d[idx * 2 + 1] = __floats2bfloat162_rn(v.z, v.w);
    }
}

// ---------------- Kernel 3: fused GEMM + exp + row/col reduce (symmetric, 1D grid) ----------------
__device__ __forceinline__ void load_tile(uint32_t sbase, const __nv_bfloat16* gbase, int kc) {
    int tid = threadIdx.x;
#pragma unroll
    for (int i = 0; i < 4; i++) {
        int idx = tid + i * 256;         // 0..1023 16B-units
        int row = idx >> 3;
        int u = idx & 7;
        const void* g = gbase + (size_t)row * DD + kc * BK + u * 8;
        uint32_t off = (uint32_t)(row * 128 + u * 16);
        cp_async16(sbase + SW128(off), g);
    }
}

__global__ void __launch_bounds__(256, 2) gemm_exp_kernel() {
    int nref = g_nref;
    int bi, bj;
    if (!map_tile(blockIdx.x, nref, &bi, &bj)) return;
    int FT = nref >> 7;                                // count of fully-ref tiles
    bool dual = (bj < FT) && (bi < bj);                // upper off-diag ref x ref tile
    int mode = (BN * (bj + 1) <= nref) ? 2 : ((BN * bj >= nref) ? 0 : 1);

    extern __shared__ char smem[];
    uint32_t sb = smem_to_u32(smem);

    int tid = threadIdx.x;
    int wid = tid >> 5, lid = tid & 31;
    int wm = wid & 3;      // warp row   (4)
    int wn = wid >> 2;     // warp col   (2)
    int grp = lid >> 2;    // groupID 0..7
    int tig = lid & 3;     // thread in group

    const __nv_bfloat16* Ab = g_perm_bf16 + (size_t)bi * BM * DD;
    const __nv_bfloat16* Bb = g_perm_bf16 + (size_t)bj * BN * DD;

    // ---- ldmatrix per-thread base offsets (within a 16KB tile) ----
    int g8 = lid >> 3, lr = lid & 7;
    uint32_t offA[2], offB[4];
#pragma unroll
    for (int mt = 0; mt < 2; mt++) {
        int row = wm * 32 + mt * 16 + (g8 & 1) * 8 + lr;
        uint32_t c = ((g8 >> 1) * 16) ^ ((row & 7) * 16);
        offA[mt] = (uint32_t)(row * 128) + c;
    }
#pragma unroll
    for (int ntp = 0; ntp < 4; ntp++) {
        int row = wn * 64 + ntp * 16 + (g8 >> 1) * 8 + lr;
        uint32_t c = ((g8 & 1) * 16) ^ ((row & 7) * 16);
        offB[ntp] = (uint32_t)(row * 128) + c;
    }

    float acc[2][8][4];
#pragma unroll
    for (int mt = 0; mt < 2; mt++)
#pragma unroll
        for (int nt = 0; nt < 8; nt++)
#pragma unroll
            for (int e = 0; e < 4; e++) acc[mt][nt][e] = 0.0f;

    // Prologue: chunk 0 -> stage 0
    load_tile(sb, Ab, 0);
    load_tile(sb + 16384, Bb, 0);
    CP_COMMIT();

    for (int c = 0; c < NCH; c++) {
        int s = c & 1;
        if (c + 1 < NCH) {
            int t2 = s ^ 1;
            load_tile(sb + t2 * STAGE_BYTES, Ab, c + 1);
            load_tile(sb + t2 * STAGE_BYTES + 16384, Bb, c + 1);
            CP_COMMIT();
            CP_WAIT(1);
        } else {
            CP_WAIT(0);
        }
        __syncthreads();

        uint32_t As = sb + s * STAGE_BYTES;
        uint32_t Bs = As + 16384;
#pragma unroll
        for (int kk = 0; kk < 4; kk++) {
            uint32_t xk = (uint32_t)(kk << 5);
            uint32_t a[2][4], b[8][2];
            ldsm_x4(a[0], (As + offA[0]) ^ xk);
            ldsm_x4(a[1], (As + offA[1]) ^ xk);
#pragma unroll
            for (int ntp = 0; ntp < 4; ntp++) {
                uint32_t r[4];
                ldsm_x4(r, (Bs + offB[ntp]) ^ xk);
                b[2 * ntp][0] = r[0]; b[2 * ntp][1] = r[1];
                b[2 * ntp + 1][0] = r[2]; b[2 * ntp + 1][1] = r[3];
            }
#pragma unroll
            for (int mt = 0; mt < 2; mt++)
#pragma unroll
                for (int nt = 0; nt < 8; nt++)
                    mma16816(acc[mt][nt], a[mt], b[nt]);
        }
        __syncthreads();
    }

    // ---- Fused epilogue: exp, diag exclusion, row sums (+ col sums if dual) ----
    float cs[8][2];
    if (dual) {
#pragma unroll
        for (int nt = 0; nt < 8; nt++) { cs[nt][0] = 0.0f; cs[nt][1] = 0.0f; }
    }

#pragma unroll
    for (int mt = 0; mt < 2; mt++) {
        int ri_lo = bi * BM + wm * 32 + mt * 16 + grp;   // permuted row index
        int ri_hi = ri_lo + 8;
        float sa0 = 0.f, sp0 = 0.f, sa1 = 0.f, sp1 = 0.f;
#pragma unroll
        for (int nt = 0; nt < 8; nt++) {
            int c0 = wn * 64 + nt * 8 + tig * 2;
#pragma unroll
            for (int e = 0; e < 2; e++) {
                int jg = bj * BN + c0 + e;               // permuted col index
                float elo = __expf(10.0f * acc[mt][nt][e]);
                if (jg == ri_lo) elo = 0.0f;             // self-similarity
                float ehi = __expf(10.0f * acc[mt][nt][2 + e]);
                if (jg == ri_hi) ehi = 0.0f;
                sa0 += elo;
                sa1 += ehi;
                if (mode == 1) {
                    float l = (jg < nref) ? 1.0f : 0.0f;
                    sp0 += elo * l;
                    sp1 += ehi * l;
                }
                if (dual) cs[nt][e] += elo + ehi;        // column partial (rows are refs)
            }
        }
#pragma unroll
        for (int o = 1; o < 4; o <<= 1) {
            sa0 += __shfl_xor_sync(0xffffffff, sa0, o);
            sa1 += __shfl_xor_sync(0xffffffff, sa1, o);
        }
        if (mode == 1) {
#pragma unroll
            for (int o = 1; o < 4; o <<= 1) {
                sp0 += __shfl_xor_sync(0xffffffff, sp0, o);
                sp1 += __shfl_xor_sync(0xffffffff, sp1, o);
            }
        }
        if (tig == 0) {
            float p0 = (mode == 2) ? sa0 : sp0;
            float p1 = (mode == 2) ? sa1 : sp1;
            if (ri_lo < nref) {
                atomicAdd(&g_all[ri_lo], sa0);
                if (mode != 0) atomicAdd(&g_pos[ri_lo], p0);
            }
            if (ri_hi < nref) {
                atomicAdd(&g_all[ri_hi], sa1);
                if (mode != 0) atomicAdd(&g_pos[ri_hi], p1);
            }
        }
    }

    if (dual) {
        // Column sums -> row sums of the skipped mirror tile (pos == all there).
#pragma unroll
        for (int nt = 0; nt < 8; nt++) {
#pragma unroll
            for (int e = 0; e < 2; e++) {
                float v = cs[nt][e];
                v += __shfl_xor_sync(0xffffffff, v, 4);
                v += __shfl_xor_sync(0xffffffff, v, 8);
                v += __shfl_xor_sync(0xffffffff, v, 16);
                if (lid < 4) {
                    int col = bj * BN + wn * 64 + nt * 8 + lid * 2 + e;
                    atomicAdd(&g_all[col], v);
                    atomicAdd(&g_pos[col], v);
                }
            }
        }
    }
}

// ---------------- Kernel 4: parallel loss reduce, direct to out ----------------
__global__ void finalize_partial(float* __restrict__ out) {
    int i = blockIdx.x * blockDim.x + threadIdx.x;
    int lane = threadIdx.x & 31, warp = threadIdx.x >> 5;
    __shared__ float s_part[8];
    int nref = g_nref;
    float loss = 0.0f;
    if (nref >= 2 && i < nref) {
        loss = -__logf(g_pos[i] / (g_all[i] + 1e-8f));
    }
#pragma unroll
    for (int o = 16; o > 0; o >>= 1) loss += __shfl_xor_sync(0xffffffffu, loss, o);
    if (lane == 0) s_part[warp] = loss;
    __syncthreads();
    if (warp == 0) {
        float v = (lane < 8) ? s_part[lane] : 0.0f;
#pragma unroll
        for (int o = 4; o > 0; o >>= 1) v += __shfl_xor_sync(0xffffffffu, v, o);
        if (lane == 0 && v != 0.0f) {
            atomicAdd(out, v / fmaxf((float)nref, 1.0f));
        }
    }
}

// ---------------- Launch ----------------
extern "C" void kernel_launch(void* const* d_in, const int* in_sizes, int n_in,
                              void* d_out, int out_size) {
    const float* emb = (const float*)d_in[0];
    const int* labels = (const int*)d_in[1];
    float* out = (float*)d_out;

    compact_kernel<<<1, 1024>>>(labels, out);
    convgather_kernel<<<NN, 128>>>(emb);

    cudaFuncSetAttribute(gemm_exp_kernel, cudaFuncAttributeMaxDynamicSharedMemorySize, SMEM_BYTES);
    gemm_exp_kernel<<<MAX_TILES, 256, SMEM_BYTES>>>();

    finalize_partial<<<NN / 256, 256>>>(out);
}